// round 11
// baseline (speedup 1.0000x reference)
#include <cuda_runtime.h>
#include <cuda_bf16.h>
#include <stdint.h>
#include <math.h>

#define ND 96
#define ED 64
#define TM 64             // edges per tile (per CTA)
#define BLK 384           // edge kernel threads (12 warps), 2 CTAs/SM
#define ABLK 512          // node kernel threads
#define MAXN 65536
#define EMAX (1<<20)

__device__ __nv_bfloat16 g_P1[(size_t)MAXN * 192];   // h*W_src + bias (gate|msg)
__device__ __nv_bfloat16 g_P2[(size_t)MAXN * 192];   // h*W_dst
__device__ int g_hist[MAXN];
__device__ int g_cursor[MAXN];
__device__ int g_ssrc[EMAX];
__device__ int g_sdst[EMAX];
__device__ int g_perm[EMAX];
__device__ int g_is64;

// ---- edge kernel smem layout (per CTA, 2 CTAs/SM) ----
#define E_B3  0           // 192x64 bf16 blocked SW128 (24576)
#define E_A0  24576       // A3 buf0: 64x64 bf16 (8192)
#define E_A1  32768       // A3 buf1 (8192)
#define E_PS0 40960       // PS buf0: 64 rows x 400B bf16 (25600)
#define E_PS1 66560       // PS buf1: 25600
#define E_ACT 92160       // ACT: 64 rows x 200B bf16 (12800)
#define E_SI  104960      // 4 x (src[64]|dst[64]|perm[64]) (3072)
#define E_SMEM 108032
#define PSROW 400
#define ACTROW 200

// ---- node kernel smem ----
#define N_B 0             // 384x96(k pad 128) bf16 blocked (98304)
#define N_A 98304         // 64x96(pad 128) bf16 (16384)
#define N_SMEM 114688

#define SW128(o) ((o) ^ (((o) >> 3) & 0x70))

__device__ __forceinline__ uint32_t smem_u32(const void* p) {
    uint32_t r;
    asm("{ .reg .u64 t; cvta.to.shared.u64 t, %1; cvt.u32.u64 %0, t; }"
        : "=r"(r) : "l"(p));
    return r;
}
__device__ __forceinline__ void ldsm_x4(uint32_t* r, uint32_t addr) {
    asm volatile("ldmatrix.sync.aligned.m8n8.x4.shared.b16 {%0,%1,%2,%3}, [%4];"
        : "=r"(r[0]), "=r"(r[1]), "=r"(r[2]), "=r"(r[3]) : "r"(addr));
}
__device__ __forceinline__ void mma16816(float* c, const uint32_t* a, const uint32_t* b) {
    asm volatile("mma.sync.aligned.m16n8k16.row.col.f32.bf16.bf16.f32 "
        "{%0,%1,%2,%3}, {%4,%5,%6,%7}, {%8,%9}, {%0,%1,%2,%3};"
        : "+f"(c[0]), "+f"(c[1]), "+f"(c[2]), "+f"(c[3])
        : "r"(a[0]), "r"(a[1]), "r"(a[2]), "r"(a[3]), "r"(b[0]), "r"(b[1]));
}
__device__ __forceinline__ float act_gm(float xg, float xn) {
    float t;
    asm("tanh.approx.f32 %0, %1;" : "=f"(t) : "f"(xg * 0.5f));
    float gate = fmaf(t, 0.5f, 0.5f);
    float p;
    asm("ex2.approx.f32 %0, %1;" : "=f"(p) : "f"(-fabsf(xn) * 1.4426950408889634f));
    float l;
    asm("lg2.approx.f32 %0, %1;" : "=f"(l) : "f"(1.0f + p));
    float sp = fmaxf(xn, 0.0f) + 0.69314718055994531f * l;
    return gate * sp;
}
__device__ __forceinline__ float2 lds_bf2f(const char* p) {
    __nv_bfloat162 v = *(const __nv_bfloat162*)p;
    return __bfloat1622float2(v);
}
__device__ __forceinline__ uint32_t hadd2u(uint32_t a, uint32_t b) {
    __nv_bfloat162 r = __hadd2(*(__nv_bfloat162*)&a, *(__nv_bfloat162*)&b);
    return *(uint32_t*)&r;
}

// ---------------- init / prep / finalize ----------------
__global__ void init_kernel(float4* __restrict__ out4, const uint32_t* __restrict__ ew,
                            long long total4, int n, long long nwords) {
    long long i = (long long)blockIdx.x * blockDim.x + threadIdx.x;
    if (i < total4) out4[i] = make_float4(0.f, 0.f, 0.f, 0.f);
    if (i < n) g_hist[i] = 0;
    if (i == 0) {
        int is64 = 1;
        long long m = nwords < 256 ? nwords : 256;
        for (long long w = 1; w < m; w += 2)
            if (ew[w] != 0u) { is64 = 0; break; }
        g_is64 = is64;
    }
}

__global__ void hist_kernel(const void* __restrict__ eidx, int E) {
    int e = blockIdx.x * blockDim.x + threadIdx.x;
    if (e >= E) return;
    int d = g_is64 ? (int)((const long long*)eidx)[(long long)E + e]
                   : ((const int*)eidx)[(long long)E + e];
    atomicAdd(&g_hist[d], 1);
}

__global__ void scan_kernel(int n) {
    __shared__ int part[1024];
    const int tid = threadIdx.x;
    int chunk = (n + 1023) >> 10;
    int lo = tid * chunk;
    int hi = lo + chunk; if (hi > n) hi = n; if (lo > n) lo = n;
    int s = 0;
    for (int i = lo; i < hi; i++) s += g_hist[i];
    part[tid] = s;
    __syncthreads();
    for (int ofs = 1; ofs < 1024; ofs <<= 1) {
        int v = (tid >= ofs) ? part[tid - ofs] : 0;
        __syncthreads();
        part[tid] += v;
        __syncthreads();
    }
    int run = (tid > 0) ? part[tid - 1] : 0;
    for (int i = lo; i < hi; i++) {
        g_cursor[i] = run;
        run += g_hist[i];
    }
}

__global__ void perm_kernel(const void* __restrict__ eidx, int E) {
    int e = blockIdx.x * blockDim.x + threadIdx.x;
    if (e >= E) return;
    int s, d;
    if (g_is64) {
        s = (int)((const long long*)eidx)[e];
        d = (int)((const long long*)eidx)[(long long)E + e];
    } else {
        s = ((const int*)eidx)[e];
        d = ((const int*)eidx)[(long long)E + e];
    }
    int pos = atomicAdd(&g_cursor[d], 1);
    g_ssrc[pos] = s;
    g_sdst[pos] = d;
    g_perm[pos] = e;
}

__global__ void finalize_kernel(const float4* __restrict__ h4, float4* __restrict__ out4,
                                long long total4) {
    long long i = (long long)blockIdx.x * blockDim.x + threadIdx.x;
    if (i < total4) {
        int node = (int)(i / (ND / 4));
        float c = (float)g_hist[node];
        c = c < 1.0f ? 1.0f : c;
        float inv = 1.0f / c;
        float4 a = h4[i], b = out4[i];
        out4[i] = make_float4(a.x + b.x * inv, a.y + b.y * inv,
                              a.z + b.z * inv, a.w + b.w * inv);
    }
}

// ---------------- node precompute kernel ----------------
// P[node][384] = h[node][0:96] @ Wcat[96][384], cols: [P1 gate|P1 msg|P2 gate|P2 msg]
__global__ __launch_bounds__(ABLK, 1)
void node_kernel(const float* __restrict__ h,
                 const float* __restrict__ W_e, const float* __restrict__ b_e,
                 const float* __restrict__ W_n, const float* __restrict__ b_n, int N) {
    extern __shared__ char sm[];
    const uint32_t sbase = smem_u32(sm);
    const int tid = threadIdx.x;
    const int wid = tid >> 5, lane = tid & 31;
    const int rg = wid & 1, cg = wid >> 1;   // 2 row groups x 8 col groups (48 cols)
    const int na0 = blockIdx.x * 64;

    for (int idx = tid; idx < 384 * 64; idx += ABLK) {
        int n = idx >> 6, kp = idx & 63;
        if (kp < 48) {
            int k = kp * 2;
            float f0, f1;
            if (n < 96)       { f0 = W_e[k * 96 + n];             f1 = W_e[(k + 1) * 96 + n]; }
            else if (n < 192) { f0 = W_n[k * 96 + (n - 96)];      f1 = W_n[(k + 1) * 96 + (n - 96)]; }
            else if (n < 288) { f0 = W_e[(96 + k) * 96 + (n - 192)]; f1 = W_e[(97 + k) * 96 + (n - 192)]; }
            else              { f0 = W_n[(96 + k) * 96 + (n - 288)]; f1 = W_n[(97 + k) * 96 + (n - 288)]; }
            __nv_bfloat162 p = __floats2bfloat162_rn(f0, f1);
            uint32_t off = (uint32_t)(kp >> 5) * 49152u + (uint32_t)(n >> 3) * 1024u
                         + (uint32_t)(n & 7) * 128u + (uint32_t)(k & 63) * 2u;
            *(uint32_t*)(sm + N_B + SW128(off)) = *(uint32_t*)&p;
        }
    }
    for (int idx = tid; idx < 64 * 64; idx += ABLK) {
        int r = idx >> 6, kp = idx & 63;
        if (kp < 48) {
            int k = kp * 2, node = na0 + r;
            float f0 = 0.f, f1 = 0.f;
            if (node < N) { f0 = h[node * 96 + k]; f1 = h[node * 96 + k + 1]; }
            __nv_bfloat162 p = __floats2bfloat162_rn(f0, f1);
            uint32_t off = (uint32_t)(kp >> 5) * 8192u + (uint32_t)(r >> 3) * 1024u
                         + (uint32_t)(r & 7) * 128u + (uint32_t)(k & 63) * 2u;
            *(uint32_t*)(sm + N_A + SW128(off)) = *(uint32_t*)&p;
        }
    }
    __syncthreads();

    const int a_m = lane >> 3;
    const int a_erow = ((a_m & 1) << 3) + (lane & 7);
    const int a_khalf = a_m >> 1;
    const int b_nrow = ((a_m & 2) << 2) + (lane & 7);
    const int b_khalf = a_m & 1;

    uint32_t aBase[2], aSw[2];
    #pragma unroll
    for (int i = 0; i < 2; i++) {
        int e = 32 * rg + 16 * i + a_erow;
        aBase[i] = sbase + N_A + (uint32_t)(e >> 3) * 1024u + (uint32_t)(e & 7) * 128u;
        aSw[i] = (uint32_t)(e & 7);
    }
    uint32_t bBase[3], bSw[3];
    #pragma unroll
    for (int nb = 0; nb < 3; nb++) {
        int n = 48 * cg + 16 * nb + b_nrow;
        bBase[nb] = sbase + N_B + (uint32_t)(n >> 3) * 1024u + (uint32_t)(n & 7) * 128u;
        bSw[nb] = (uint32_t)(n & 7);
    }

    float acc[2][6][4];
    #pragma unroll
    for (int i = 0; i < 2; i++)
        #pragma unroll
        for (int b = 0; b < 6; b++)
            #pragma unroll
            for (int c = 0; c < 4; c++) acc[i][b][c] = 0.f;

    #pragma unroll
    for (int kc = 0; kc < 6; kc++) {
        uint32_t kblkA = (uint32_t)(kc >> 2) * 8192u;
        uint32_t kblkB = (uint32_t)(kc >> 2) * 49152u;
        uint32_t kc2 = (uint32_t)((kc & 3) << 1);
        uint32_t aF[2][4], bF[3][4];
        #pragma unroll
        for (int i = 0; i < 2; i++)
            ldsm_x4(aF[i], kblkA + aBase[i] + ((((kc2 | (uint32_t)a_khalf) ^ aSw[i])) << 4));
        #pragma unroll
        for (int nb = 0; nb < 3; nb++)
            ldsm_x4(bF[nb], kblkB + bBase[nb] + ((((kc2 | (uint32_t)b_khalf) ^ bSw[nb])) << 4));
        #pragma unroll
        for (int i = 0; i < 2; i++)
            #pragma unroll
            for (int nb = 0; nb < 3; nb++) {
                mma16816(acc[i][2 * nb], aF[i], bF[nb]);
                mma16816(acc[i][2 * nb + 1], aF[i], bF[nb] + 2);
            }
    }

    const int gg = lane >> 2, tt = lane & 3;
    #pragma unroll
    for (int i = 0; i < 2; i++) {
        int lr0 = 32 * rg + 16 * i + gg;
        int n0 = na0 + lr0, n1 = n0 + 8;
        #pragma unroll
        for (int b = 0; b < 6; b++) {
            int cn = 48 * cg + 8 * b + 2 * tt;
            float bias0 = 0.f, bias1 = 0.f;
            if (cn < 96)       { bias0 = b_e[cn];      bias1 = b_e[cn + 1]; }
            else if (cn < 192) { bias0 = b_n[cn - 96]; bias1 = b_n[cn - 95]; }
            __nv_bfloat16* arr = (cn < 192) ? g_P1 : g_P2;
            int cc = (cn < 192) ? cn : cn - 192;
            __nv_bfloat162 v0 = __floats2bfloat162_rn(acc[i][b][0] + bias0, acc[i][b][1] + bias1);
            __nv_bfloat162 v1 = __floats2bfloat162_rn(acc[i][b][2] + bias0, acc[i][b][3] + bias1);
            if (n0 < N) *(__nv_bfloat162*)(arr + (size_t)n0 * 192 + cc) = v0;
            if (n1 < N) *(__nv_bfloat162*)(arr + (size_t)n1 * 192 + cc) = v1;
        }
    }
}

// ---------------- edge kernel (2 CTAs/SM, dst-sorted edges) ----------------
__global__ __launch_bounds__(BLK, 2)
void edge_kernel(const float* __restrict__ edge_attr,
                 const float* __restrict__ W_e, const float* __restrict__ W_n,
                 float* __restrict__ out, int E, int ntiles) {
    extern __shared__ char sm[];
    const uint32_t sbase = smem_u32(sm);
    const int tid = threadIdx.x;
    const int wid = tid >> 5, lane = tid & 31;
    const int rg = wid & 1;          // rows [32*rg, 32*rg+32)
    const int cg = wid >> 1;         // 0..5: gate cols [16cg,+16), msg +96

    // B3 = W3 (rows 192..255 of We/Wn), [n][k] bf16 blocked SW128
    for (int idx = tid; idx < 192 * 32; idx += BLK) {
        int n = idx >> 5;
        int k = (idx & 31) * 2;
        float f0, f1;
        if (n < 96) { f0 = W_e[(192 + k) * 96 + n];        f1 = W_e[(193 + k) * 96 + n]; }
        else        { f0 = W_n[(192 + k) * 96 + (n - 96)]; f1 = W_n[(193 + k) * 96 + (n - 96)]; }
        __nv_bfloat162 p = __floats2bfloat162_rn(f0, f1);
        uint32_t off = (uint32_t)(n >> 3) * 1024u + (uint32_t)(n & 7) * 128u + (uint32_t)k * 2u;
        *(uint32_t*)(sm + E_B3 + SW128(off)) = *(uint32_t*)&p;
    }

    int* sI = (int*)(sm + E_SI);     // 4 slots x 192 ints (src[64]|dst[64]|perm[64])
    char* ACT = sm + E_ACT;

    const int a_m = lane >> 3;
    const int a_erow = ((a_m & 1) << 3) + (lane & 7);
    const int a_khalf = a_m >> 1;
    const int b_nrow = ((a_m & 2) << 2) + (lane & 7);
    const int b_khalf = a_m & 1;

    const int ng0 = 16 * cg;
    const int ng = ng0 + b_nrow;
    const int nm = ng + ND;
    const uint32_t bgBase = sbase + E_B3 + (uint32_t)(ng >> 3) * 1024u + (uint32_t)(ng & 7) * 128u;
    const uint32_t bgSw = (uint32_t)(ng & 7);
    const uint32_t bmBase = sbase + E_B3 + (uint32_t)(nm >> 3) * 1024u + (uint32_t)(nm & 7) * 128u;
    const uint32_t bmSw = (uint32_t)(nm & 7);

    const int grid = gridDim.x;
    const int bid = blockIdx.x;
    const int nloc = (ntiles - bid + grid - 1) / grid;
    const int gg = lane >> 2, tt = lane & 3;

    // PS chunk decomposition: thread t -> (e0 = t/24, c = t%24), e += 16 per step.
    const int ps_e0 = tid / 24;
    const int ps_c  = tid - ps_e0 * 24;     // 0..23

    // flush decomposition: col + quarter
    const int fl_c = tid % 96;
    const int fl_q = (tid / 96) * 16;

    #define STAGE_IDX(slot, tile)  do { \
        if (tid < 192) { \
            int which = tid >> 6, e = tid & 63; \
            long long eg = (long long)(tile) * TM + e; \
            int v; \
            if (eg < (long long)E) \
                v = (which == 0) ? g_ssrc[eg] : (which == 1) ? g_sdst[eg] : g_perm[eg]; \
            else \
                v = (which == 2) ? 0 : -1; \
            sI[(slot) * 192 + tid] = v; \
        } \
    } while (0)

    #define GATHER_A3(aoff, slot, tile) do { \
        const int* sIp = sI + (slot) * 192 + 128; \
        long long ebb = (long long)(tile) * TM; \
        for (int idx = tid; idx < 1024; idx += BLK) { \
            int e = idx >> 4, k4 = (idx & 15) << 2; \
            float4 x = make_float4(0.f, 0.f, 0.f, 0.f); \
            if (ebb + e < (long long)E) { \
                int p_ = sIp[e]; \
                x = *(const float4*)(edge_attr + (size_t)p_ * ED + k4); \
            } \
            __nv_bfloat162 p0 = __floats2bfloat162_rn(x.x, x.y); \
            __nv_bfloat162 p1 = __floats2bfloat162_rn(x.z, x.w); \
            uint2 u = make_uint2(*(uint32_t*)&p0, *(uint32_t*)&p1); \
            uint32_t off = (uint32_t)(e >> 3) * 1024u + (uint32_t)(e & 7) * 128u + (uint32_t)k4 * 2u; \
            *(uint2*)(sm + (aoff) + SW128(off)) = u; \
        } \
    } while (0)

    // prologue
    STAGE_IDX(0, bid);
    __syncthreads();
    GATHER_A3(E_A0, 0, bid);
    if (nloc > 1) STAGE_IDX(1, bid + grid);
    __syncthreads();

    for (int L = 0; L < nloc; L++) {
        const int* sIL = sI + (L & 3) * 192;
        const uint32_t saAb = sbase + ((L & 1) ? E_A1 : E_A0);
        char* psb = sm + ((L & 1) ? E_PS1 : E_PS0);

        // ---- a. PS stage: PS = P1[src] + P2[dst] (bf16 add), coalesced chunks ----
        {
            #pragma unroll
            for (int i = 0; i < 4; i++) {
                int e = ps_e0 + 16 * i;         // 0..63
                int src = sIL[e], dst = sIL[TM + e];
                if (src >= 0) {
                    uint4 a = *(const uint4*)(g_P1 + (size_t)src * 192 + ps_c * 8);
                    uint4 b = *(const uint4*)(g_P2 + (size_t)dst * 192 + ps_c * 8);
                    uint4 s;
                    s.x = hadd2u(a.x, b.x);
                    s.y = hadd2u(a.y, b.y);
                    s.z = hadd2u(a.z, b.z);
                    s.w = hadd2u(a.w, b.w);
                    *(uint4*)(psb + (uint32_t)e * PSROW + (uint32_t)ps_c * 16) = s;
                }
            }
        }

        // ---- b. MMA: z3 = A3 @ B3, K=64 ----
        float cgx[2][2][4], cm[2][2][4];
        #pragma unroll
        for (int i = 0; i < 2; i++)
            #pragma unroll
            for (int j = 0; j < 2; j++)
                #pragma unroll
                for (int c = 0; c < 4; c++) { cgx[i][j][c] = 0.f; cm[i][j][c] = 0.f; }

        uint32_t aBase[2], aSw[2];
        #pragma unroll
        for (int i = 0; i < 2; i++) {
            int e = 32 * rg + 16 * i + a_erow;
            aBase[i] = saAb + (uint32_t)(e >> 3) * 1024u + (uint32_t)(e & 7) * 128u;
            aSw[i] = (uint32_t)(e & 7);
        }
        #pragma unroll
        for (int kc = 0; kc < 4; kc++) {
            uint32_t kc2 = (uint32_t)(kc << 1);
            uint32_t aF[2][4], bg[4], bm[4];
            #pragma unroll
            for (int i = 0; i < 2; i++)
                ldsm_x4(aF[i], aBase[i] + (((kc2 | (uint32_t)a_khalf) ^ aSw[i]) << 4));
            ldsm_x4(bg, bgBase + (((kc2 | (uint32_t)b_khalf) ^ bgSw) << 4));
            ldsm_x4(bm, bmBase + (((kc2 | (uint32_t)b_khalf) ^ bmSw) << 4));
            #pragma unroll
            for (int i = 0; i < 2; i++) {
                mma16816(cgx[i][0], aF[i], bg);
                mma16816(cgx[i][1], aF[i], bg + 2);
                mma16816(cm[i][0], aF[i], bm);
                mma16816(cm[i][1], aF[i], bm + 2);
            }
        }

        // ---- c. stage next tile ----
        if (L + 1 < nloc) {
            GATHER_A3((L & 1) ? E_A0 : E_A1, (L + 1) & 3, bid + (L + 1) * grid);
            if (L + 2 < nloc) STAGE_IDX((L + 2) & 3, bid + (L + 2) * grid);
        }

        __syncthreads();   // d. commits PS(L), A3(L+1), idx(L+2)

        // ---- e. epilogue: z = acc + PS; act; store bf16 to ACT ----
        #pragma unroll
        for (int i = 0; i < 2; i++) {
            int lr0 = 32 * rg + 16 * i + gg;
            int lr1 = lr0 + 8;
            const char* r0p = psb + lr0 * PSROW;
            const char* r1p = psb + lr1 * PSROW;
            #pragma unroll
            for (int j = 0; j < 2; j++) {
                int c = ng0 + 8 * j + 2 * tt;
                float2 g0 = lds_bf2f(r0p + 2 * c);
                float2 m0 = lds_bf2f(r0p + 2 * c + 192);
                float2 g1 = lds_bf2f(r1p + 2 * c);
                float2 m1 = lds_bf2f(r1p + 2 * c + 192);
                float v00 = act_gm(cgx[i][j][0] + g0.x, cm[i][j][0] + m0.x);
                float v01 = act_gm(cgx[i][j][1] + g0.y, cm[i][j][1] + m0.y);
                float v10 = act_gm(cgx[i][j][2] + g1.x, cm[i][j][2] + m1.x);
                float v11 = act_gm(cgx[i][j][3] + g1.y, cm[i][j][3] + m1.y);
                __nv_bfloat162 p0 = __floats2bfloat162_rn(v00, v01);
                __nv_bfloat162 p1 = __floats2bfloat162_rn(v10, v11);
                *(uint32_t*)(ACT + lr0 * ACTROW + 2 * c) = *(uint32_t*)&p0;
                *(uint32_t*)(ACT + lr1 * ACTROW + 2 * c) = *(uint32_t*)&p1;
            }
        }

        __syncthreads();   // f. ACT committed

        // ---- g. segmented flush: each thread owns (col, 16-row quarter) ----
        {
            const int* dsts = sIL + TM;
            float acc = 0.0f;
            int dcur = dsts[fl_q];
            #pragma unroll
            for (int r = fl_q; r < fl_q + 16; r++) {
                int d = dsts[r];
                __nv_bfloat16 vb = *(const __nv_bfloat16*)(ACT + r * ACTROW + 2 * fl_c);
                float v = __bfloat162float(vb);
                if (d != dcur) {
                    if (dcur >= 0)
                        asm volatile("red.global.add.f32 [%0], %1;"
                            :: "l"(out + (long long)dcur * ND + fl_c), "f"(acc) : "memory");
                    acc = 0.0f;
                    dcur = d;
                }
                acc += v;
            }
            if (dcur >= 0)
                asm volatile("red.global.add.f32 [%0], %1;"
                    :: "l"(out + (long long)dcur * ND + fl_c), "f"(acc) : "memory");
        }
        // no trailing barrier: next writes to ACT/psb/sI slots occur only after
        // barriers that order them behind this flush (4-deep sI ring).
    }
    #undef STAGE_IDX
    #undef GATHER_A3
}

extern "C" void kernel_launch(void* const* d_in, const int* in_sizes, int n_in,
                              void* d_out, int out_size) {
    const float* h   = (const float*)d_in[0];
    const void*  ei  = d_in[1];
    const float* ea  = (const float*)d_in[2];
    const float* W_e = (const float*)d_in[3];
    const float* b_e = (const float*)d_in[4];
    const float* W_n = (const float*)d_in[5];
    const float* b_n = (const float*)d_in[6];
    float* out = (float*)d_out;

    int N = in_sizes[0] / ND;
    int E = in_sizes[2] / ED;
    long long total4 = (long long)N * ND / 4;
    long long nwords = (long long)in_sizes[1];

    int ib = (int)((total4 + 255) / 256);
    init_kernel<<<ib, 256>>>((float4*)out, (const uint32_t*)ei, total4, N, nwords);

    int eb = (E + 255) / 256;
    hist_kernel<<<eb, 256>>>(ei, E);
    scan_kernel<<<1, 1024>>>(N);
    perm_kernel<<<eb, 256>>>(ei, E);

    int nblocks = (N + 63) / 64;
    cudaFuncSetAttribute(node_kernel, cudaFuncAttributeMaxDynamicSharedMemorySize, N_SMEM);
    node_kernel<<<nblocks, ABLK, N_SMEM>>>(h, W_e, b_e, W_n, b_n, N);

    int ntiles = (E + TM - 1) / TM;
    cudaFuncSetAttribute(edge_kernel, cudaFuncAttributeMaxDynamicSharedMemorySize, E_SMEM);
    int grid = ntiles < 296 ? ntiles : 296;
    edge_kernel<<<grid, BLK, E_SMEM>>>(ea, W_e, W_n, out, E, ntiles);

    finalize_kernel<<<ib, 256>>>((const float4*)h, (float4*)out, total4);
}

// round 12
// speedup vs baseline: 1.1776x; 1.1776x over previous
#include <cuda_runtime.h>
#include <cuda_bf16.h>
#include <stdint.h>
#include <math.h>

#define ND 96
#define ED 64
#define TM 64             // edges per tile (per CTA)
#define BLK 384           // edge kernel threads (12 warps), 2 CTAs/SM
#define ABLK 512          // node kernel threads
#define MAXN 65536

// P layout per node: 192 bf16, interleaved pairs [g0,g1,m0,m1, g2,g3,m2,m3, ...]
__device__ __nv_bfloat16 g_P1[(size_t)MAXN * 192];   // h*W_src + bias
__device__ __nv_bfloat16 g_P2[(size_t)MAXN * 192];   // h*W_dst
__device__ float g_cnt[MAXN];
__device__ int g_is64;

// ---- edge kernel smem layout (per CTA, 2 CTAs/SM) ----
#define E_B3  0           // 192x64 bf16 blocked SW128 (24576)
#define E_A0  24576       // A3 buf0: 64x64 bf16 (8192)
#define E_A1  32768       // A3 buf1 (8192)
#define E_PS0 40960       // PS buf0: 64 rows x 400B bf16 (25600)
#define E_PS1 66560       // PS buf1: 25600
#define E_SI  92160       // 3 x (src[64]|dst[64]) (1536)
#define E_SMEM 93696
#define PSROW 400

// ---- node kernel smem ----
#define N_B 0             // 384x96(k pad 128) bf16 blocked (98304)
#define N_A 98304         // 64x96(pad 128) bf16 (16384)
#define N_SMEM 114688

#define SW128(o) ((o) ^ (((o) >> 3) & 0x70))

__device__ __forceinline__ uint32_t smem_u32(const void* p) {
    uint32_t r;
    asm("{ .reg .u64 t; cvta.to.shared.u64 t, %1; cvt.u32.u64 %0, t; }"
        : "=r"(r) : "l"(p));
    return r;
}
__device__ __forceinline__ void ldsm_x4(uint32_t* r, uint32_t addr) {
    asm volatile("ldmatrix.sync.aligned.m8n8.x4.shared.b16 {%0,%1,%2,%3}, [%4];"
        : "=r"(r[0]), "=r"(r[1]), "=r"(r[2]), "=r"(r[3]) : "r"(addr));
}
__device__ __forceinline__ void mma16816(float* c, const uint32_t* a, const uint32_t* b) {
    asm volatile("mma.sync.aligned.m16n8k16.row.col.f32.bf16.bf16.f32 "
        "{%0,%1,%2,%3}, {%4,%5,%6,%7}, {%8,%9}, {%0,%1,%2,%3};"
        : "+f"(c[0]), "+f"(c[1]), "+f"(c[2]), "+f"(c[3])
        : "r"(a[0]), "r"(a[1]), "r"(a[2]), "r"(a[3]), "r"(b[0]), "r"(b[1]));
}
__device__ __forceinline__ float act_gm(float xg, float xn) {
    float t;
    asm("tanh.approx.f32 %0, %1;" : "=f"(t) : "f"(xg * 0.5f));
    float gate = fmaf(t, 0.5f, 0.5f);
    float p;
    asm("ex2.approx.f32 %0, %1;" : "=f"(p) : "f"(-fabsf(xn) * 1.4426950408889634f));
    float l;
    asm("lg2.approx.f32 %0, %1;" : "=f"(l) : "f"(1.0f + p));
    float sp = fmaxf(xn, 0.0f) + 0.69314718055994531f * l;
    return gate * sp;
}
__device__ __forceinline__ float2 bf2f(uint32_t u) {
    return __bfloat1622float2(*(__nv_bfloat162*)&u);
}
__device__ __forceinline__ uint32_t hadd2u(uint32_t a, uint32_t b) {
    __nv_bfloat162 r = __hadd2(*(__nv_bfloat162*)&a, *(__nv_bfloat162*)&b);
    return *(uint32_t*)&r;
}

// ---------------- init / finalize ----------------
__global__ void init_kernel(float4* __restrict__ out4, const uint32_t* __restrict__ ew,
                            long long total4, int n, long long nwords) {
    long long i = (long long)blockIdx.x * blockDim.x + threadIdx.x;
    if (i < total4) out4[i] = make_float4(0.f, 0.f, 0.f, 0.f);
    if (i < n) g_cnt[i] = 0.0f;
    if (i == 0) {
        int is64 = 1;
        long long m = nwords < 256 ? nwords : 256;
        for (long long w = 1; w < m; w += 2)
            if (ew[w] != 0u) { is64 = 0; break; }
        g_is64 = is64;
    }
}

__global__ void finalize_kernel(const float4* __restrict__ h4, float4* __restrict__ out4,
                                long long total4) {
    long long i = (long long)blockIdx.x * blockDim.x + threadIdx.x;
    if (i < total4) {
        int node = (int)(i / (ND / 4));
        float c = g_cnt[node];
        c = c < 1.0f ? 1.0f : c;
        float inv = 1.0f / c;
        float4 a = h4[i], b = out4[i];
        out4[i] = make_float4(a.x + b.x * inv, a.y + b.y * inv,
                              a.z + b.z * inv, a.w + b.w * inv);
    }
}

// ---------------- node precompute kernel ----------------
// P[node] = h[node] @ Wcat, stored INTERLEAVED: pair c -> [g_c,g_{c+1},m_c,m_{c+1}]
__global__ __launch_bounds__(ABLK, 1)
void node_kernel(const float* __restrict__ h,
                 const float* __restrict__ W_e, const float* __restrict__ b_e,
                 const float* __restrict__ W_n, const float* __restrict__ b_n, int N) {
    extern __shared__ char sm[];
    const uint32_t sbase = smem_u32(sm);
    const int tid = threadIdx.x;
    const int wid = tid >> 5, lane = tid & 31;
    const int rg = wid & 1, cg = wid >> 1;   // 2 row groups x 8 col groups (48 cols)
    const int na0 = blockIdx.x * 64;

    for (int idx = tid; idx < 384 * 64; idx += ABLK) {
        int n = idx >> 6, kp = idx & 63;
        if (kp < 48) {
            int k = kp * 2;
            float f0, f1;
            if (n < 96)       { f0 = W_e[k * 96 + n];             f1 = W_e[(k + 1) * 96 + n]; }
            else if (n < 192) { f0 = W_n[k * 96 + (n - 96)];      f1 = W_n[(k + 1) * 96 + (n - 96)]; }
            else if (n < 288) { f0 = W_e[(96 + k) * 96 + (n - 192)]; f1 = W_e[(97 + k) * 96 + (n - 192)]; }
            else              { f0 = W_n[(96 + k) * 96 + (n - 288)]; f1 = W_n[(97 + k) * 96 + (n - 288)]; }
            __nv_bfloat162 p = __floats2bfloat162_rn(f0, f1);
            uint32_t off = (uint32_t)(kp >> 5) * 49152u + (uint32_t)(n >> 3) * 1024u
                         + (uint32_t)(n & 7) * 128u + (uint32_t)(k & 63) * 2u;
            *(uint32_t*)(sm + N_B + SW128(off)) = *(uint32_t*)&p;
        }
    }
    for (int idx = tid; idx < 64 * 64; idx += ABLK) {
        int r = idx >> 6, kp = idx & 63;
        if (kp < 48) {
            int k = kp * 2, node = na0 + r;
            float f0 = 0.f, f1 = 0.f;
            if (node < N) { f0 = h[node * 96 + k]; f1 = h[node * 96 + k + 1]; }
            __nv_bfloat162 p = __floats2bfloat162_rn(f0, f1);
            uint32_t off = (uint32_t)(kp >> 5) * 8192u + (uint32_t)(r >> 3) * 1024u
                         + (uint32_t)(r & 7) * 128u + (uint32_t)(k & 63) * 2u;
            *(uint32_t*)(sm + N_A + SW128(off)) = *(uint32_t*)&p;
        }
    }
    __syncthreads();

    const int a_m = lane >> 3;
    const int a_erow = ((a_m & 1) << 3) + (lane & 7);
    const int a_khalf = a_m >> 1;
    const int b_nrow = ((a_m & 2) << 2) + (lane & 7);
    const int b_khalf = a_m & 1;

    uint32_t aBase[2], aSw[2];
    #pragma unroll
    for (int i = 0; i < 2; i++) {
        int e = 32 * rg + 16 * i + a_erow;
        aBase[i] = sbase + N_A + (uint32_t)(e >> 3) * 1024u + (uint32_t)(e & 7) * 128u;
        aSw[i] = (uint32_t)(e & 7);
    }
    uint32_t bBase[3], bSw[3];
    #pragma unroll
    for (int nb = 0; nb < 3; nb++) {
        int n = 48 * cg + 16 * nb + b_nrow;
        bBase[nb] = sbase + N_B + (uint32_t)(n >> 3) * 1024u + (uint32_t)(n & 7) * 128u;
        bSw[nb] = (uint32_t)(n & 7);
    }

    float acc[2][6][4];
    #pragma unroll
    for (int i = 0; i < 2; i++)
        #pragma unroll
        for (int b = 0; b < 6; b++)
            #pragma unroll
            for (int c = 0; c < 4; c++) acc[i][b][c] = 0.f;

    #pragma unroll
    for (int kc = 0; kc < 6; kc++) {
        uint32_t kblkA = (uint32_t)(kc >> 2) * 8192u;
        uint32_t kblkB = (uint32_t)(kc >> 2) * 49152u;
        uint32_t kc2 = (uint32_t)((kc & 3) << 1);
        uint32_t aF[2][4], bF[3][4];
        #pragma unroll
        for (int i = 0; i < 2; i++)
            ldsm_x4(aF[i], kblkA + aBase[i] + ((((kc2 | (uint32_t)a_khalf) ^ aSw[i])) << 4));
        #pragma unroll
        for (int nb = 0; nb < 3; nb++)
            ldsm_x4(bF[nb], kblkB + bBase[nb] + ((((kc2 | (uint32_t)b_khalf) ^ bSw[nb])) << 4));
        #pragma unroll
        for (int i = 0; i < 2; i++)
            #pragma unroll
            for (int nb = 0; nb < 3; nb++) {
                mma16816(acc[i][2 * nb], aF[i], bF[nb]);
                mma16816(acc[i][2 * nb + 1], aF[i], bF[nb] + 2);
            }
    }

    const int gg = lane >> 2, tt = lane & 3;
    #pragma unroll
    for (int i = 0; i < 2; i++) {
        int lr0 = 32 * rg + 16 * i + gg;
        int n0 = na0 + lr0, n1 = n0 + 8;
        #pragma unroll
        for (int b = 0; b < 6; b++) {
            int cn = 48 * cg + 8 * b + 2 * tt;     // even, 0..382
            float bias0 = 0.f, bias1 = 0.f;
            if (cn < 96)       { bias0 = b_e[cn];      bias1 = b_e[cn + 1]; }
            else if (cn < 192) { bias0 = b_n[cn - 96]; bias1 = b_n[cn - 95]; }
            __nv_bfloat16* arr = (cn < 192) ? g_P1 : g_P2;
            int cc = (cn < 192) ? cn : cn - 192;   // 0..190 even
            // interleaved position: gate pair c -> (c>>1)*4 ; msg pair c -> (c>>1)*4+2
            int pos = (cc < 96) ? ((cc >> 1) << 2) : ((((cc - 96) >> 1) << 2) + 2);
            __nv_bfloat162 v0 = __floats2bfloat162_rn(acc[i][b][0] + bias0, acc[i][b][1] + bias1);
            __nv_bfloat162 v1 = __floats2bfloat162_rn(acc[i][b][2] + bias0, acc[i][b][3] + bias1);
            if (n0 < N) *(__nv_bfloat162*)(arr + (size_t)n0 * 192 + pos) = v0;
            if (n1 < N) *(__nv_bfloat162*)(arr + (size_t)n1 * 192 + pos) = v1;
        }
    }
}

// ---------------- edge kernel (2 CTAs/SM) ----------------
__global__ __launch_bounds__(BLK, 2)
void edge_kernel(const void* __restrict__ eidx,
                 const float* __restrict__ edge_attr,
                 const float* __restrict__ W_e, const float* __restrict__ W_n,
                 float* __restrict__ out, int E, int ntiles) {
    extern __shared__ char sm[];
    const uint32_t sbase = smem_u32(sm);
    const int tid = threadIdx.x;
    const int wid = tid >> 5, lane = tid & 31;
    const int rg = wid & 1;          // rows [32*rg, 32*rg+32)
    const int cg = wid >> 1;         // 0..5: gate cols [16cg,+16), msg +96

    // B3 = W3 (rows 192..255 of We/Wn), [n][k] bf16 blocked SW128
    for (int idx = tid; idx < 192 * 32; idx += BLK) {
        int n = idx >> 5;
        int k = (idx & 31) * 2;
        float f0, f1;
        if (n < 96) { f0 = W_e[(192 + k) * 96 + n];        f1 = W_e[(193 + k) * 96 + n]; }
        else        { f0 = W_n[(192 + k) * 96 + (n - 96)]; f1 = W_n[(193 + k) * 96 + (n - 96)]; }
        __nv_bfloat162 p = __floats2bfloat162_rn(f0, f1);
        uint32_t off = (uint32_t)(n >> 3) * 1024u + (uint32_t)(n & 7) * 128u + (uint32_t)k * 2u;
        *(uint32_t*)(sm + E_B3 + SW128(off)) = *(uint32_t*)&p;
    }

    const int is64 = g_is64;
    const long long* e64 = (const long long*)eidx;
    const int*       e32 = (const int*)eidx;
    int* sI = (int*)(sm + E_SI);     // 3 slots x 128 ints (src[64]|dst[64])

    const int a_m = lane >> 3;
    const int a_erow = ((a_m & 1) << 3) + (lane & 7);
    const int a_khalf = a_m >> 1;
    const int b_nrow = ((a_m & 2) << 2) + (lane & 7);
    const int b_khalf = a_m & 1;

    const int ng0 = 16 * cg;
    const int ng = ng0 + b_nrow;
    const int nm = ng + ND;
    const uint32_t bgBase = sbase + E_B3 + (uint32_t)(ng >> 3) * 1024u + (uint32_t)(ng & 7) * 128u;
    const uint32_t bgSw = (uint32_t)(ng & 7);
    const uint32_t bmBase = sbase + E_B3 + (uint32_t)(nm >> 3) * 1024u + (uint32_t)(nm & 7) * 128u;
    const uint32_t bmSw = (uint32_t)(nm & 7);

    const int grid = gridDim.x;
    const int bid = blockIdx.x;
    const int nloc = (ntiles - bid + grid - 1) / grid;
    const int gg = lane >> 2, tt = lane & 3;
    const int ttOdd = tt & 1;

    // PS chunk decomposition: thread t -> (e0 = t/24, c = t%24), e += 16 per step.
    const int ps_e0 = tid / 24;
    const int ps_c  = tid - ps_e0 * 24;     // 0..23

    #define STAGE_IDX(slot, tile)  do { \
        if (tid < 2 * TM) { \
            int which = tid >> 6, e = tid & 63; \
            long long eg = (long long)(tile) * TM + e; \
            int v = -1; \
            if (eg < (long long)E) { \
                long long pos = (long long)which * E + eg; \
                v = is64 ? (int)e64[pos] : e32[pos]; \
            } \
            sI[(slot) * 128 + tid] = v; \
            if (which && v >= 0) atomicAdd(&g_cnt[v], 1.0f); \
        } \
    } while (0)

    #define GATHER_A3(aoff, tile) do { \
        int eb_ = (tile) * TM; \
        for (int idx = tid; idx < 1024; idx += BLK) { \
            int e = idx >> 4, k4 = (idx & 15) << 2; \
            long long eg = (long long)eb_ + e; \
            float4 x = make_float4(0.f, 0.f, 0.f, 0.f); \
            if (eg < (long long)E) x = *(const float4*)(edge_attr + eg * ED + k4); \
            __nv_bfloat162 p0 = __floats2bfloat162_rn(x.x, x.y); \
            __nv_bfloat162 p1 = __floats2bfloat162_rn(x.z, x.w); \
            uint2 u = make_uint2(*(uint32_t*)&p0, *(uint32_t*)&p1); \
            uint32_t off = (uint32_t)(e >> 3) * 1024u + (uint32_t)(e & 7) * 128u + (uint32_t)k4 * 2u; \
            *(uint2*)(sm + (aoff) + SW128(off)) = u; \
        } \
    } while (0)

    // prologue
    STAGE_IDX(0, bid);
    __syncthreads();

    // hoist B fragments into registers (loop-invariant)
    uint32_t bgR[4][4], bmR[4][4];
    #pragma unroll
    for (int kc = 0; kc < 4; kc++) {
        uint32_t kc2 = (uint32_t)(kc << 1);
        ldsm_x4(bgR[kc], bgBase + (((kc2 | (uint32_t)b_khalf) ^ bgSw) << 4));
        ldsm_x4(bmR[kc], bmBase + (((kc2 | (uint32_t)b_khalf) ^ bmSw) << 4));
    }

    GATHER_A3(E_A0, bid);
    if (nloc > 1) STAGE_IDX(1, bid + grid);
    __syncthreads();

    for (int L = 0; L < nloc; L++) {
        const int* sIL = sI + (L % 3) * 128;
        const uint32_t saAb = sbase + ((L & 1) ? E_A1 : E_A0);
        char* psb = sm + ((L & 1) ? E_PS1 : E_PS0);

        int dstA[2], dstB[2];
        #pragma unroll
        for (int i = 0; i < 2; i++) {
            int lr = 32 * rg + 16 * i + gg;
            dstA[i] = sIL[TM + lr];
            dstB[i] = sIL[TM + lr + 8];
        }

        // ---- a. PS stage: PS = P1[src] + P2[dst] (bf16 add), coalesced chunks ----
        {
            #pragma unroll
            for (int i = 0; i < 4; i++) {
                int e = ps_e0 + 16 * i;         // 0..63
                int src = sIL[e], dst = sIL[TM + e];
                if (src >= 0) {
                    uint4 a = *(const uint4*)(g_P1 + (size_t)src * 192 + ps_c * 8);
                    uint4 b = *(const uint4*)(g_P2 + (size_t)dst * 192 + ps_c * 8);
                    uint4 s;
                    s.x = hadd2u(a.x, b.x);
                    s.y = hadd2u(a.y, b.y);
                    s.z = hadd2u(a.z, b.z);
                    s.w = hadd2u(a.w, b.w);
                    *(uint4*)(psb + (uint32_t)e * PSROW + (uint32_t)ps_c * 16) = s;
                }
            }
        }

        // ---- b. stage next tile EARLY (gather LDGs hide under MMA) ----
        if (L + 1 < nloc) {
            GATHER_A3((L & 1) ? E_A0 : E_A1, bid + (L + 1) * grid);
            if (L + 2 < nloc) STAGE_IDX((L + 2) % 3, bid + (L + 2) * grid);
        }

        // ---- c. MMA: z3 = A3 @ B3, K=64 (B from registers) ----
        float cgx[2][2][4], cm[2][2][4];
        #pragma unroll
        for (int i = 0; i < 2; i++)
            #pragma unroll
            for (int j = 0; j < 2; j++)
                #pragma unroll
                for (int c = 0; c < 4; c++) { cgx[i][j][c] = 0.f; cm[i][j][c] = 0.f; }

        uint32_t aBase[2], aSw[2];
        #pragma unroll
        for (int i = 0; i < 2; i++) {
            int e = 32 * rg + 16 * i + a_erow;
            aBase[i] = saAb + (uint32_t)(e >> 3) * 1024u + (uint32_t)(e & 7) * 128u;
            aSw[i] = (uint32_t)(e & 7);
        }
        #pragma unroll
        for (int kc = 0; kc < 4; kc++) {
            uint32_t kc2 = (uint32_t)(kc << 1);
            uint32_t aF[2][4];
            #pragma unroll
            for (int i = 0; i < 2; i++)
                ldsm_x4(aF[i], aBase[i] + (((kc2 | (uint32_t)a_khalf) ^ aSw[i]) << 4));
            #pragma unroll
            for (int i = 0; i < 2; i++) {
                mma16816(cgx[i][0], aF[i], bgR[kc]);
                mma16816(cgx[i][1], aF[i], bgR[kc] + 2);
                mma16816(cm[i][0], aF[i], bmR[kc]);
                mma16816(cm[i][1], aF[i], bmR[kc] + 2);
            }
        }

        __syncthreads();   // d. single barrier: commits PS(L), A3(L+1), idx(L+2)

        // ---- e. epilogue: z = acc + PS (interleaved LDS.64); act; butterfly v4 RED ----
        #pragma unroll
        for (int i = 0; i < 2; i++) {
            int lr0 = 32 * rg + 16 * i + gg;
            int lr1 = lr0 + 8;
            int dst0 = dstA[i], dst1 = dstB[i];
            const char* r0p = psb + lr0 * PSROW;
            const char* r1p = psb + lr1 * PSROW;
            #pragma unroll
            for (int j = 0; j < 2; j++) {
                int c = ng0 + 8 * j + 2 * tt;   // even
                uint2 w0 = *(const uint2*)(r0p + 4 * c);   // [g_c,g_c+1, m_c,m_c+1]
                uint2 w1 = *(const uint2*)(r1p + 4 * c);
                float2 g0 = bf2f(w0.x), m0 = bf2f(w0.y);
                float2 g1 = bf2f(w1.x), m1 = bf2f(w1.y);
                float v00 = act_gm(cgx[i][j][0] + g0.x, cm[i][j][0] + m0.x);
                float v01 = act_gm(cgx[i][j][1] + g0.y, cm[i][j][1] + m0.y);
                float v10 = act_gm(cgx[i][j][2] + g1.x, cm[i][j][2] + m1.x);
                float v11 = act_gm(cgx[i][j][3] + g1.y, cm[i][j][3] + m1.y);
                float s0 = ttOdd ? v00 : v10;
                float s1 = ttOdd ? v01 : v11;
                float r0 = __shfl_xor_sync(0xffffffffu, s0, 1);
                float r1 = __shfl_xor_sync(0xffffffffu, s1, 1);
                int colbase = ng0 + 8 * j + (tt >> 1) * 4;
                if (!ttOdd) {
                    if (dst0 >= 0)
                        asm volatile("red.global.add.v4.f32 [%0], {%1,%2,%3,%4};"
                            :: "l"(out + (long long)dst0 * ND + colbase),
                               "f"(v00), "f"(v01), "f"(r0), "f"(r1) : "memory");
                } else {
                    if (dst1 >= 0)
                        asm volatile("red.global.add.v4.f32 [%0], {%1,%2,%3,%4};"
                            :: "l"(out + (long long)dst1 * ND + colbase),
                               "f"(r0), "f"(r1), "f"(v10), "f"(v11) : "memory");
                }
            }
        }
        // no trailing barrier: PS/A3 double-buffered, idx ring depth 3,
        // dst indices already registered before the mid-tile barrier.
    }
    #undef STAGE_IDX
    #undef GATHER_A3
}

extern "C" void kernel_launch(void* const* d_in, const int* in_sizes, int n_in,
                              void* d_out, int out_size) {
    const float* h   = (const float*)d_in[0];
    const void*  ei  = d_in[1];
    const float* ea  = (const float*)d_in[2];
    const float* W_e = (const float*)d_in[3];
    const float* b_e = (const float*)d_in[4];
    const float* W_n = (const float*)d_in[5];
    const float* b_n = (const float*)d_in[6];
    float* out = (float*)d_out;

    int N = in_sizes[0] / ND;
    int E = in_sizes[2] / ED;
    long long total4 = (long long)N * ND / 4;
    long long nwords = (long long)in_sizes[1];

    int ib = (int)((total4 + 255) / 256);
    init_kernel<<<ib, 256>>>((float4*)out, (const uint32_t*)ei, total4, N, nwords);

    int nblocks = (N + 63) / 64;
    cudaFuncSetAttribute(node_kernel, cudaFuncAttributeMaxDynamicSharedMemorySize, N_SMEM);
    node_kernel<<<nblocks, ABLK, N_SMEM>>>(h, W_e, b_e, W_n, b_n, N);

    int ntiles = (E + TM - 1) / TM;
    cudaFuncSetAttribute(edge_kernel, cudaFuncAttributeMaxDynamicSharedMemorySize, E_SMEM);
    int grid = ntiles < 296 ? ntiles : 296;
    edge_kernel<<<grid, BLK, E_SMEM>>>(ei, ea, W_e, W_n, out, E, ntiles);

    finalize_kernel<<<ib, 256>>>((const float4*)h, (float4*)out, total4);
}

// round 14
// speedup vs baseline: 1.3273x; 1.1271x over previous
#include <cuda_runtime.h>
#include <cuda_bf16.h>
#include <stdint.h>
#include <math.h>

#define ND 96
#define ED 64
#define TM 64             // edges per tile (per CTA)
#define BLK 384           // edge kernel threads (12 warps), 2 CTAs/SM
#define ABLK 512          // node kernel threads
#define MAXN 65536

// P layout per node: 192 bf16, interleaved pairs [g0,g1,m0,m1, g2,g3,m2,m3, ...]
__device__ __nv_bfloat16 g_P1[(size_t)MAXN * 192];   // h*W_src + bias
__device__ __nv_bfloat16 g_P2[(size_t)MAXN * 192];   // h*W_dst
__device__ float g_cnt[MAXN];
__device__ int g_is64;

// ---- edge kernel smem layout (per CTA, 2 CTAs/SM) ----
#define E_B3  0           // 192x64 bf16 blocked SW128 (24576)
#define E_A0  24576       // A3 buf0: 64x64 bf16 (8192)
#define E_A1  32768       // A3 buf1 (8192)
#define E_PS0 40960       // PS buf0: 64 rows x 400B bf16 (25600)
#define E_PS1 66560       // PS buf1: 25600
#define E_SI  92160       // 3 x (src[64]|dst[64]) (1536)
#define E_SMEM 93696
#define PSROW 400

// ---- node kernel smem ----
#define N_B 0             // 384x96(k pad 128) bf16 blocked (98304)
#define N_A 98304         // 64x96(pad 128) bf16 (16384)
#define N_SMEM 114688

#define SW128(o) ((o) ^ (((o) >> 3) & 0x70))

__device__ __forceinline__ uint32_t smem_u32(const void* p) {
    uint32_t r;
    asm("{ .reg .u64 t; cvta.to.shared.u64 t, %1; cvt.u32.u64 %0, t; }"
        : "=r"(r) : "l"(p));
    return r;
}
__device__ __forceinline__ void ldsm_x4(uint32_t* r, uint32_t addr) {
    asm volatile("ldmatrix.sync.aligned.m8n8.x4.shared.b16 {%0,%1,%2,%3}, [%4];"
        : "=r"(r[0]), "=r"(r[1]), "=r"(r[2]), "=r"(r[3]) : "r"(addr));
}
__device__ __forceinline__ void mma16816(float* c, const uint32_t* a, const uint32_t* b) {
    asm volatile("mma.sync.aligned.m16n8k16.row.col.f32.bf16.bf16.f32 "
        "{%0,%1,%2,%3}, {%4,%5,%6,%7}, {%8,%9}, {%0,%1,%2,%3};"
        : "+f"(c[0]), "+f"(c[1]), "+f"(c[2]), "+f"(c[3])
        : "r"(a[0]), "r"(a[1]), "r"(a[2]), "r"(a[3]), "r"(b[0]), "r"(b[1]));
}
__device__ __forceinline__ float act_gm(float xg, float xn) {
    float t;
    asm("tanh.approx.f32 %0, %1;" : "=f"(t) : "f"(xg * 0.5f));
    float gate = fmaf(t, 0.5f, 0.5f);
    float p;
    asm("ex2.approx.f32 %0, %1;" : "=f"(p) : "f"(-fabsf(xn) * 1.4426950408889634f));
    float l;
    asm("lg2.approx.f32 %0, %1;" : "=f"(l) : "f"(1.0f + p));
    float sp = fmaxf(xn, 0.0f) + 0.69314718055994531f * l;
    return gate * sp;
}
__device__ __forceinline__ float2 bf2f(uint32_t u) {
    return __bfloat1622float2(*(__nv_bfloat162*)&u);
}
__device__ __forceinline__ uint32_t hadd2u(uint32_t a, uint32_t b) {
    __nv_bfloat162 r = __hadd2(*(__nv_bfloat162*)&a, *(__nv_bfloat162*)&b);
    return *(uint32_t*)&r;
}
// 32-byte L2-policy loads (ptxas requires v4.b64 width with evict modifiers)
__device__ __forceinline__ void ldg_el8(const void* p, uint32_t v[8]) {
    unsigned long long a, b, c, d;
    asm volatile("ld.global.L2::evict_last.v4.b64 {%0,%1,%2,%3}, [%4];"
        : "=l"(a), "=l"(b), "=l"(c), "=l"(d) : "l"(p));
    v[0] = (uint32_t)a; v[1] = (uint32_t)(a >> 32);
    v[2] = (uint32_t)b; v[3] = (uint32_t)(b >> 32);
    v[4] = (uint32_t)c; v[5] = (uint32_t)(c >> 32);
    v[6] = (uint32_t)d; v[7] = (uint32_t)(d >> 32);
}
__device__ __forceinline__ void ldg_ef8f(const float* p, float f[8]) {
    unsigned long long a, b, c, d;
    asm volatile("ld.global.L2::evict_first.v4.b64 {%0,%1,%2,%3}, [%4];"
        : "=l"(a), "=l"(b), "=l"(c), "=l"(d) : "l"(p));
    uint32_t w[8] = { (uint32_t)a, (uint32_t)(a >> 32), (uint32_t)b, (uint32_t)(b >> 32),
                      (uint32_t)c, (uint32_t)(c >> 32), (uint32_t)d, (uint32_t)(d >> 32) };
    #pragma unroll
    for (int i = 0; i < 8; i++) f[i] = __uint_as_float(w[i]);
}

// ---------------- init / finalize ----------------
__global__ void init_kernel(float4* __restrict__ out4, const uint32_t* __restrict__ ew,
                            long long total4, int n, long long nwords) {
    long long i = (long long)blockIdx.x * blockDim.x + threadIdx.x;
    if (i < total4) out4[i] = make_float4(0.f, 0.f, 0.f, 0.f);
    if (i < n) g_cnt[i] = 0.0f;
    if (i == 0) {
        int is64 = 1;
        long long m = nwords < 256 ? nwords : 256;
        for (long long w = 1; w < m; w += 2)
            if (ew[w] != 0u) { is64 = 0; break; }
        g_is64 = is64;
    }
}

__global__ void finalize_kernel(const float4* __restrict__ h4, float4* __restrict__ out4,
                                long long total4) {
    long long i = (long long)blockIdx.x * blockDim.x + threadIdx.x;
    if (i < total4) {
        int node = (int)(i / (ND / 4));
        float c = g_cnt[node];
        c = c < 1.0f ? 1.0f : c;
        float inv = 1.0f / c;
        float4 a = h4[i], b = out4[i];
        out4[i] = make_float4(a.x + b.x * inv, a.y + b.y * inv,
                              a.z + b.z * inv, a.w + b.w * inv);
    }
}

// ---------------- node precompute kernel ----------------
// P[node] = h[node] @ Wcat, stored INTERLEAVED: pair c -> [g_c,g_{c+1},m_c,m_{c+1}]
__global__ __launch_bounds__(ABLK, 1)
void node_kernel(const float* __restrict__ h,
                 const float* __restrict__ W_e, const float* __restrict__ b_e,
                 const float* __restrict__ W_n, const float* __restrict__ b_n, int N) {
    extern __shared__ char sm[];
    const uint32_t sbase = smem_u32(sm);
    const int tid = threadIdx.x;
    const int wid = tid >> 5, lane = tid & 31;
    const int rg = wid & 1, cg = wid >> 1;   // 2 row groups x 8 col groups (48 cols)
    const int na0 = blockIdx.x * 64;

    for (int idx = tid; idx < 384 * 64; idx += ABLK) {
        int n = idx >> 6, kp = idx & 63;
        if (kp < 48) {
            int k = kp * 2;
            float f0, f1;
            if (n < 96)       { f0 = W_e[k * 96 + n];             f1 = W_e[(k + 1) * 96 + n]; }
            else if (n < 192) { f0 = W_n[k * 96 + (n - 96)];      f1 = W_n[(k + 1) * 96 + (n - 96)]; }
            else if (n < 288) { f0 = W_e[(96 + k) * 96 + (n - 192)]; f1 = W_e[(97 + k) * 96 + (n - 192)]; }
            else              { f0 = W_n[(96 + k) * 96 + (n - 288)]; f1 = W_n[(97 + k) * 96 + (n - 288)]; }
            __nv_bfloat162 p = __floats2bfloat162_rn(f0, f1);
            uint32_t off = (uint32_t)(kp >> 5) * 49152u + (uint32_t)(n >> 3) * 1024u
                         + (uint32_t)(n & 7) * 128u + (uint32_t)(k & 63) * 2u;
            *(uint32_t*)(sm + N_B + SW128(off)) = *(uint32_t*)&p;
        }
    }
    for (int idx = tid; idx < 64 * 64; idx += ABLK) {
        int r = idx >> 6, kp = idx & 63;
        if (kp < 48) {
            int k = kp * 2, node = na0 + r;
            float f0 = 0.f, f1 = 0.f;
            if (node < N) { f0 = h[node * 96 + k]; f1 = h[node * 96 + k + 1]; }
            __nv_bfloat162 p = __floats2bfloat162_rn(f0, f1);
            uint32_t off = (uint32_t)(kp >> 5) * 8192u + (uint32_t)(r >> 3) * 1024u
                         + (uint32_t)(r & 7) * 128u + (uint32_t)(k & 63) * 2u;
            *(uint32_t*)(sm + N_A + SW128(off)) = *(uint32_t*)&p;
        }
    }
    __syncthreads();

    const int a_m = lane >> 3;
    const int a_erow = ((a_m & 1) << 3) + (lane & 7);
    const int a_khalf = a_m >> 1;
    const int b_nrow = ((a_m & 2) << 2) + (lane & 7);
    const int b_khalf = a_m & 1;

    uint32_t aBase[2], aSw[2];
    #pragma unroll
    for (int i = 0; i < 2; i++) {
        int e = 32 * rg + 16 * i + a_erow;
        aBase[i] = sbase + N_A + (uint32_t)(e >> 3) * 1024u + (uint32_t)(e & 7) * 128u;
        aSw[i] = (uint32_t)(e & 7);
    }
    uint32_t bBase[3], bSw[3];
    #pragma unroll
    for (int nb = 0; nb < 3; nb++) {
        int n = 48 * cg + 16 * nb + b_nrow;
        bBase[nb] = sbase + N_B + (uint32_t)(n >> 3) * 1024u + (uint32_t)(n & 7) * 128u;
        bSw[nb] = (uint32_t)(n & 7);
    }

    float acc[2][6][4];
    #pragma unroll
    for (int i = 0; i < 2; i++)
        #pragma unroll
        for (int b = 0; b < 6; b++)
            #pragma unroll
            for (int c = 0; c < 4; c++) acc[i][b][c] = 0.f;

    #pragma unroll
    for (int kc = 0; kc < 6; kc++) {
        uint32_t kblkA = (uint32_t)(kc >> 2) * 8192u;
        uint32_t kblkB = (uint32_t)(kc >> 2) * 49152u;
        uint32_t kc2 = (uint32_t)((kc & 3) << 1);
        uint32_t aF[2][4], bF[3][4];
        #pragma unroll
        for (int i = 0; i < 2; i++)
            ldsm_x4(aF[i], kblkA + aBase[i] + ((((kc2 | (uint32_t)a_khalf) ^ aSw[i])) << 4));
        #pragma unroll
        for (int nb = 0; nb < 3; nb++)
            ldsm_x4(bF[nb], kblkB + bBase[nb] + ((((kc2 | (uint32_t)b_khalf) ^ bSw[nb])) << 4));
        #pragma unroll
        for (int i = 0; i < 2; i++)
            #pragma unroll
            for (int nb = 0; nb < 3; nb++) {
                mma16816(acc[i][2 * nb], aF[i], bF[nb]);
                mma16816(acc[i][2 * nb + 1], aF[i], bF[nb] + 2);
            }
    }

    const int gg = lane >> 2, tt = lane & 3;
    #pragma unroll
    for (int i = 0; i < 2; i++) {
        int lr0 = 32 * rg + 16 * i + gg;
        int n0 = na0 + lr0, n1 = n0 + 8;
        #pragma unroll
        for (int b = 0; b < 6; b++) {
            int cn = 48 * cg + 8 * b + 2 * tt;     // even, 0..382
            float bias0 = 0.f, bias1 = 0.f;
            if (cn < 96)       { bias0 = b_e[cn];      bias1 = b_e[cn + 1]; }
            else if (cn < 192) { bias0 = b_n[cn - 96]; bias1 = b_n[cn - 95]; }
            __nv_bfloat16* arr = (cn < 192) ? g_P1 : g_P2;
            int cc = (cn < 192) ? cn : cn - 192;   // 0..190 even
            int pos = (cc < 96) ? ((cc >> 1) << 2) : ((((cc - 96) >> 1) << 2) + 2);
            __nv_bfloat162 v0 = __floats2bfloat162_rn(acc[i][b][0] + bias0, acc[i][b][1] + bias1);
            __nv_bfloat162 v1 = __floats2bfloat162_rn(acc[i][b][2] + bias0, acc[i][b][3] + bias1);
            if (n0 < N) *(__nv_bfloat162*)(arr + (size_t)n0 * 192 + pos) = v0;
            if (n1 < N) *(__nv_bfloat162*)(arr + (size_t)n1 * 192 + pos) = v1;
        }
    }
}

// ---------------- edge kernel (2 CTAs/SM) ----------------
__global__ __launch_bounds__(BLK, 2)
void edge_kernel(const void* __restrict__ eidx,
                 const float* __restrict__ edge_attr,
                 const float* __restrict__ W_e, const float* __restrict__ W_n,
                 float* __restrict__ out, int E, int ntiles) {
    extern __shared__ char sm[];
    const uint32_t sbase = smem_u32(sm);
    const int tid = threadIdx.x;
    const int wid = tid >> 5, lane = tid & 31;
    const int rg = wid & 1;          // rows [32*rg, 32*rg+32)
    const int cg = wid >> 1;         // 0..5: gate cols [16cg,+16), msg +96

    // B3 = W3 (rows 192..255 of We/Wn), [n][k] bf16 blocked SW128
    for (int idx = tid; idx < 192 * 32; idx += BLK) {
        int n = idx >> 5;
        int k = (idx & 31) * 2;
        float f0, f1;
        if (n < 96) { f0 = W_e[(192 + k) * 96 + n];        f1 = W_e[(193 + k) * 96 + n]; }
        else        { f0 = W_n[(192 + k) * 96 + (n - 96)]; f1 = W_n[(193 + k) * 96 + (n - 96)]; }
        __nv_bfloat162 p = __floats2bfloat162_rn(f0, f1);
        uint32_t off = (uint32_t)(n >> 3) * 1024u + (uint32_t)(n & 7) * 128u + (uint32_t)k * 2u;
        *(uint32_t*)(sm + E_B3 + SW128(off)) = *(uint32_t*)&p;
    }

    const int is64 = g_is64;
    const long long* e64 = (const long long*)eidx;
    const int*       e32 = (const int*)eidx;
    int* sI = (int*)(sm + E_SI);     // 3 slots x 128 ints (src[64]|dst[64])

    const int a_m = lane >> 3;
    const int a_erow = ((a_m & 1) << 3) + (lane & 7);
    const int a_khalf = a_m >> 1;
    const int b_nrow = ((a_m & 2) << 2) + (lane & 7);
    const int b_khalf = a_m & 1;

    const int ng0 = 16 * cg;
    const int ng = ng0 + b_nrow;
    const int nm = ng + ND;
    const uint32_t bgBase = sbase + E_B3 + (uint32_t)(ng >> 3) * 1024u + (uint32_t)(ng & 7) * 128u;
    const uint32_t bgSw = (uint32_t)(ng & 7);
    const uint32_t bmBase = sbase + E_B3 + (uint32_t)(nm >> 3) * 1024u + (uint32_t)(nm & 7) * 128u;
    const uint32_t bmSw = (uint32_t)(nm & 7);

    const int grid = gridDim.x;
    const int bid = blockIdx.x;
    const int nloc = (ntiles - bid + grid - 1) / grid;
    const int gg = lane >> 2, tt = lane & 3;
    const int ttOdd = tt & 1;

    // PS chunk decomposition: 64 edges x 12 chunks of 32B; thread t -> (e0=t/12, c=t%12),
    // e advances by 32 per step (384 = 32*12): 2 steps cover 64 edges.
    const int ps_e0 = tid / 12;
    const int ps_c  = tid - ps_e0 * 12;     // 0..11 (32B units within 384B row)

    #define STAGE_IDX(slot, tile)  do { \
        if (tid < 2 * TM) { \
            int which = tid >> 6, e = tid & 63; \
            long long eg = (long long)(tile) * TM + e; \
            int v = -1; \
            if (eg < (long long)E) { \
                long long pos = (long long)which * E + eg; \
                v = is64 ? (int)e64[pos] : e32[pos]; \
            } \
            sI[(slot) * 128 + tid] = v; \
            if (which && v >= 0) atomicAdd(&g_cnt[v], 1.0f); \
        } \
    } while (0)

    // A3 gather: 64 edges x 8 chunks of 32B = 512 chunks
    #define GATHER_A3(aoff, tile) do { \
        int eb_ = (tile) * TM; \
        for (int idx = tid; idx < 512; idx += BLK) { \
            int e = idx >> 3, k8 = (idx & 7) << 3; \
            long long eg = (long long)eb_ + e; \
            float f[8] = {0.f,0.f,0.f,0.f,0.f,0.f,0.f,0.f}; \
            if (eg < (long long)E) ldg_ef8f(edge_attr + eg * ED + k8, f); \
            __nv_bfloat162 q0 = __floats2bfloat162_rn(f[0], f[1]); \
            __nv_bfloat162 q1 = __floats2bfloat162_rn(f[2], f[3]); \
            __nv_bfloat162 q2 = __floats2bfloat162_rn(f[4], f[5]); \
            __nv_bfloat162 q3 = __floats2bfloat162_rn(f[6], f[7]); \
            uint4 u = make_uint4(*(uint32_t*)&q0, *(uint32_t*)&q1, \
                                 *(uint32_t*)&q2, *(uint32_t*)&q3); \
            uint32_t off = (uint32_t)(e >> 3) * 1024u + (uint32_t)(e & 7) * 128u + (uint32_t)k8 * 2u; \
            *(uint4*)(sm + (aoff) + SW128(off)) = u; \
        } \
    } while (0)

    // prologue
    STAGE_IDX(0, bid);
    __syncthreads();

    // hoist B fragments into registers (loop-invariant)
    uint32_t bgR[4][4], bmR[4][4];
    #pragma unroll
    for (int kc = 0; kc < 4; kc++) {
        uint32_t kc2 = (uint32_t)(kc << 1);
        ldsm_x4(bgR[kc], bgBase + (((kc2 | (uint32_t)b_khalf) ^ bgSw) << 4));
        ldsm_x4(bmR[kc], bmBase + (((kc2 | (uint32_t)b_khalf) ^ bmSw) << 4));
    }

    GATHER_A3(E_A0, bid);
    if (nloc > 1) STAGE_IDX(1, bid + grid);
    __syncthreads();

    for (int L = 0; L < nloc; L++) {
        const int* sIL = sI + (L % 3) * 128;
        const uint32_t saAb = sbase + ((L & 1) ? E_A1 : E_A0);
        char* psb = sm + ((L & 1) ? E_PS1 : E_PS0);

        int dstA[2], dstB[2];
        #pragma unroll
        for (int i = 0; i < 2; i++) {
            int lr = 32 * rg + 16 * i + gg;
            dstA[i] = sIL[TM + lr];
            dstB[i] = sIL[TM + lr + 8];
        }

        // ---- a. PS stage: PS = P1[src] + P2[dst] (bf16 add), L2-pinned 32B loads ----
        {
            #pragma unroll
            for (int i = 0; i < 2; i++) {
                int e = ps_e0 + 32 * i;         // 0..63
                int src = sIL[e], dst = sIL[TM + e];
                if (src >= 0) {
                    uint32_t a[8], b[8];
                    ldg_el8(g_P1 + (size_t)src * 192 + ps_c * 16, a);
                    ldg_el8(g_P2 + (size_t)dst * 192 + ps_c * 16, b);
                    uint32_t s[8];
                    #pragma unroll
                    for (int q = 0; q < 8; q++) s[q] = hadd2u(a[q], b[q]);
                    char* dstp = psb + (uint32_t)e * PSROW + (uint32_t)ps_c * 32;
                    *(uint4*)(dstp)      = make_uint4(s[0], s[1], s[2], s[3]);
                    *(uint4*)(dstp + 16) = make_uint4(s[4], s[5], s[6], s[7]);
                }
            }
        }

        // ---- b. stage next tile EARLY (gather LDGs hide under MMA) ----
        if (L + 1 < nloc) {
            GATHER_A3((L & 1) ? E_A0 : E_A1, bid + (L + 1) * grid);
            if (L + 2 < nloc) STAGE_IDX((L + 2) % 3, bid + (L + 2) * grid);
        }

        // ---- c. MMA: z3 = A3 @ B3, K=64 (B from registers) ----
        float cgx[2][2][4], cm[2][2][4];
        #pragma unroll
        for (int i = 0; i < 2; i++)
            #pragma unroll
            for (int j = 0; j < 2; j++)
                #pragma unroll
                for (int c = 0; c < 4; c++) { cgx[i][j][c] = 0.f; cm[i][j][c] = 0.f; }

        uint32_t aBase[2], aSw[2];
        #pragma unroll
        for (int i = 0; i < 2; i++) {
            int e = 32 * rg + 16 * i + a_erow;
            aBase[i] = saAb + (uint32_t)(e >> 3) * 1024u + (uint32_t)(e & 7) * 128u;
            aSw[i] = (uint32_t)(e & 7);
        }
        #pragma unroll
        for (int kc = 0; kc < 4; kc++) {
            uint32_t kc2 = (uint32_t)(kc << 1);
            uint32_t aF[2][4];
            #pragma unroll
            for (int i = 0; i < 2; i++)
                ldsm_x4(aF[i], aBase[i] + (((kc2 | (uint32_t)a_khalf) ^ aSw[i]) << 4));
            #pragma unroll
            for (int i = 0; i < 2; i++) {
                mma16816(cgx[i][0], aF[i], bgR[kc]);
                mma16816(cgx[i][1], aF[i], bgR[kc] + 2);
                mma16816(cm[i][0], aF[i], bmR[kc]);
                mma16816(cm[i][1], aF[i], bmR[kc] + 2);
            }
        }

        __syncthreads();   // d. single barrier: commits PS(L), A3(L+1), idx(L+2)

        // ---- e. epilogue: z = acc + PS (interleaved LDS.64); act; butterfly v4 RED ----
        #pragma unroll
        for (int i = 0; i < 2; i++) {
            int lr0 = 32 * rg + 16 * i + gg;
            int lr1 = lr0 + 8;
            int dst0 = dstA[i], dst1 = dstB[i];
            const char* r0p = psb + lr0 * PSROW;
            const char* r1p = psb + lr1 * PSROW;
            #pragma unroll
            for (int j = 0; j < 2; j++) {
                int c = ng0 + 8 * j + 2 * tt;   // even
                uint2 w0 = *(const uint2*)(r0p + 4 * c);
                uint2 w1 = *(const uint2*)(r1p + 4 * c);
                float2 g0 = bf2f(w0.x), m0 = bf2f(w0.y);
                float2 g1 = bf2f(w1.x), m1 = bf2f(w1.y);
                float v00 = act_gm(cgx[i][j][0] + g0.x, cm[i][j][0] + m0.x);
                float v01 = act_gm(cgx[i][j][1] + g0.y, cm[i][j][1] + m0.y);
                float v10 = act_gm(cgx[i][j][2] + g1.x, cm[i][j][2] + m1.x);
                float v11 = act_gm(cgx[i][j][3] + g1.y, cm[i][j][3] + m1.y);
                float s0 = ttOdd ? v00 : v10;
                float s1 = ttOdd ? v01 : v11;
                float r0 = __shfl_xor_sync(0xffffffffu, s0, 1);
                float r1 = __shfl_xor_sync(0xffffffffu, s1, 1);
                int colbase = ng0 + 8 * j + (tt >> 1) * 4;
                if (!ttOdd) {
                    if (dst0 >= 0)
                        asm volatile("red.global.add.v4.f32 [%0], {%1,%2,%3,%4};"
                            :: "l"(out + (long long)dst0 * ND + colbase),
                               "f"(v00), "f"(v01), "f"(r0), "f"(r1) : "memory");
                } else {
                    if (dst1 >= 0)
                        asm volatile("red.global.add.v4.f32 [%0], {%1,%2,%3,%4};"
                            :: "l"(out + (long long)dst1 * ND + colbase),
                               "f"(r0), "f"(r1), "f"(v10), "f"(v11) : "memory");
                }
            }
        }
        // no trailing barrier: PS/A3 double-buffered, idx ring depth 3,
        // dst indices already registered before the mid-tile barrier.
    }
    #undef STAGE_IDX
    #undef GATHER_A3
}

extern "C" void kernel_launch(void* const* d_in, const int* in_sizes, int n_in,
                              void* d_out, int out_size) {
    const float* h   = (const float*)d_in[0];
    const void*  ei  = d_in[1];
    const float* ea  = (const float*)d_in[2];
    const float* W_e = (const float*)d_in[3];
    const float* b_e = (const float*)d_in[4];
    const float* W_n = (const float*)d_in[5];
    const float* b_n = (const float*)d_in[6];
    float* out = (float*)d_out;

    int N = in_sizes[0] / ND;
    int E = in_sizes[2] / ED;
    long long total4 = (long long)N * ND / 4;
    long long nwords = (long long)in_sizes[1];

    int ib = (int)((total4 + 255) / 256);
    init_kernel<<<ib, 256>>>((float4*)out, (const uint32_t*)ei, total4, N, nwords);

    int nblocks = (N + 63) / 64;
    cudaFuncSetAttribute(node_kernel, cudaFuncAttributeMaxDynamicSharedMemorySize, N_SMEM);
    node_kernel<<<nblocks, ABLK, N_SMEM>>>(h, W_e, b_e, W_n, b_n, N);

    int ntiles = (E + TM - 1) / TM;
    cudaFuncSetAttribute(edge_kernel, cudaFuncAttributeMaxDynamicSharedMemorySize, E_SMEM);
    int grid = ntiles < 296 ? ntiles : 296;
    edge_kernel<<<grid, BLK, E_SMEM>>>(ei, ea, W_e, W_n, out, E, ntiles);

    finalize_kernel<<<ib, 256>>>((const float4*)h, (float4*)out, total4);
}